// round 10
// baseline (speedup 1.0000x reference)
#include <cuda_runtime.h>
#include <cuda_fp16.h>
#include <math.h>
#include <stdint.h>

// ---------------- problem constants ----------------
#define HM   2048      // B*S = 4*512 rows
#define DD   768       // feature dim
#define K1   1536      // 2*D (concat real/imag)
#define NC   1000      // concepts
#define NCP  1024      // padded
#define NV   50000     // vocab
#define NVP  50176     // padded (392 tiles of 128)
#define TOPK 5
#define NCAND 32       // rescore candidate count (single-term fp16 filter -> wide net)

// ---------------- scratch (static device allocs are legal) ----------------
__device__ __align__(256) __half g_xhi[HM*K1];
__device__ __align__(256) __half g_xlo[HM*K1];
__device__ __align__(256) __half g_mhi[HM*DD];
__device__ __align__(256) float  g_minv[HM];
__device__ __align__(256) __half g_chi[NCP*DD];
__device__ __align__(256) float  g_cinv[NCP];
__device__ __align__(256) __half g_w1hi[DD*K1];
__device__ __align__(256) __half g_w1lo[DD*K1];
__device__ __align__(256) __half g_w2hi[512*DD];
__device__ __align__(256) __half g_w2lo[512*DD];
__device__ __align__(256) __half g_w3hi[DD*512];
__device__ __align__(256) __half g_w3lo[DD*512];
__device__ __align__(256) __half g_w4t[(size_t)NVP*DD];
__device__ __align__(256) float  g_sims[(size_t)HM*NCP];
__device__ __align__(256) __half g_h1hi[HM*DD];
__device__ __align__(256) __half g_h1lo[HM*DD];
__device__ __align__(256) __half g_h2hi[HM*512];
__device__ __align__(256) __half g_h2lo[HM*512];
__device__ __align__(256) __half g_h3[HM*DD];
// exact-path buffers for fp64 rescoring
__device__ __align__(256) float  g_magf [HM*DD];
__device__ __align__(256) float  g_cmagf[NC*DD];
__device__ __align__(256) double g_mnorm_d[HM];
__device__ __align__(256) double g_cnorm_d[NCP];

// ---------------- helpers ----------------
__device__ __forceinline__ uint32_t cvta_s(const void* p){
    return (uint32_t)__cvta_generic_to_shared(p);
}
#define CP_ASYNC(dst, src) asm volatile("cp.async.cg.shared.global [%0], [%1], 16;\n" :: "r"(dst), "l"(src))
#define CP_COMMIT          asm volatile("cp.async.commit_group;\n" ::)
#define CP_WAIT1           asm volatile("cp.async.wait_group 1;\n" ::)
#define CP_WAIT0           asm volatile("cp.async.wait_group 0;\n" ::)

__device__ __forceinline__ float gelu_f(float x){
    return 0.5f * x * (1.0f + erff(x * 0.7071067811865475f));
}

// reference-matching fp32 magnitude: r*r, i*i, add, sqrt — all RN, NO fma contraction
__device__ __forceinline__ float mag_ref(float r, float i){
    return __fsqrt_rn(__fadd_rn(__fmul_rn(r, r), __fmul_rn(i, i)));
}

// ---------------- prep kernels ----------------
// transpose + fp32 -> fp16 hi/lo split:  W[K,N] row-major  ->  Wt[Npad,K]
__global__ void wconv_kernel(const float* __restrict__ W, __half* __restrict__ outHi,
                             __half* __restrict__ outLo, int K, int N, int Npad)
{
    __shared__ float tile[32][33];
    int k0 = blockIdx.y * 32, n0 = blockIdx.x * 32;
    int tx = threadIdx.x, ty = threadIdx.y;
    #pragma unroll
    for(int i = 0; i < 32; i += 8){
        int k = k0 + ty + i, n = n0 + tx;
        tile[ty + i][tx] = (n < N) ? W[(size_t)k * N + n] : 0.f;
    }
    __syncthreads();
    #pragma unroll
    for(int i = 0; i < 32; i += 8){
        int n = n0 + ty + i, k = k0 + tx;
        if(n < Npad){
            float v = tile[tx][ty + i];
            __half h = __float2half(v);
            outHi[(size_t)n * K + k] = h;
            if(outLo) outLo[(size_t)n * K + k] = __float2half(v - __half2float(h));
        }
    }
}

// per-row: x = [re, im] hi/lo split; mag (ref-exact fp32) fp16 + fp32 copy; fp64 norm
__global__ void prep_x_kernel(const float* __restrict__ re, const float* __restrict__ im)
{
    int row = blockIdx.x, tid = threadIdx.x;
    __shared__ double red[256];
    double ss = 0.0;
    for(int d = tid; d < DD; d += 256){
        float r  = re[(size_t)row * DD + d];
        float ii = im[(size_t)row * DD + d];
        __half hr = __float2half(r);
        __half hi2 = __float2half(ii);
        g_xhi[(size_t)row * K1 + d]      = hr;
        g_xlo[(size_t)row * K1 + d]      = __float2half(r - __half2float(hr));
        g_xhi[(size_t)row * K1 + DD + d] = hi2;
        g_xlo[(size_t)row * K1 + DD + d] = __float2half(ii - __half2float(hi2));
        float m = mag_ref(r, ii);
        g_magf[(size_t)row * DD + d] = m;
        ss = fma((double)m, (double)m, ss);
        g_mhi[(size_t)row * DD + d] = __float2half(m);
    }
    red[tid] = ss; __syncthreads();
    for(int s = 128; s > 0; s >>= 1){ if(tid < s) red[tid] += red[tid + s]; __syncthreads(); }
    if(tid == 0){
        double n = sqrt(red[0]);
        if(n < 1e-8) n = 1e-8;
        g_mnorm_d[row] = n;
        g_minv[row] = (float)(1.0 / n);
    }
}

__global__ void prep_c_kernel(const float* __restrict__ cre, const float* __restrict__ cim)
{
    int row = blockIdx.x, tid = threadIdx.x;
    __shared__ double red[256];
    double ss = 0.0;
    for(int d = tid; d < DD; d += 256){
        float m = 0.f;
        if(row < NC){
            float r = cre[(size_t)row * DD + d];
            float ii = cim[(size_t)row * DD + d];
            m = mag_ref(r, ii);
            g_cmagf[(size_t)row * DD + d] = m;
        }
        ss = fma((double)m, (double)m, ss);
        g_chi[(size_t)row * DD + d] = __float2half(m);
    }
    red[tid] = ss; __syncthreads();
    for(int s = 128; s > 0; s >>= 1){ if(tid < s) red[tid] += red[tid + s]; __syncthreads(); }
    if(tid == 0){
        double n = sqrt(red[0]);
        if(n < 1e-8) n = 1e-8;
        g_cnorm_d[row] = n;
        g_cinv[row] = (float)(1.0 / n);
    }
}

// ---------------- top-k: candidate filter (approx sims) + fp64 rescore ----------------
__global__ void topk_rescore(float* __restrict__ osims, float* __restrict__ oidx)
{
    int row = blockIdx.x;
    int tid = threadIdx.x, lane = tid & 31, warp = tid >> 5;
    __shared__ int    cand[NCAND];
    __shared__ double sval[NCAND];

    if(warp == 0){
        const float* s = g_sims + (size_t)row * NCP;
        float v[32];
        #pragma unroll
        for(int j = 0; j < 32; j++){
            int idx = j * 32 + lane;
            v[j] = (idx < NC) ? s[idx] : -3.0e38f;
        }
        for(int k = 0; k < NCAND; k++){
            float best = -3.0e38f; int bi = 1 << 20;
            #pragma unroll
            for(int j = 0; j < 32; j++){
                int idx = j * 32 + lane;
                if(v[j] > best){ best = v[j]; bi = idx; }
            }
            #pragma unroll
            for(int off = 16; off; off >>= 1){
                float ov = __shfl_xor_sync(0xffffffffu, best, off);
                int   oi = __shfl_xor_sync(0xffffffffu, bi,   off);
                if(ov > best || (ov == best && oi < bi)){ best = ov; bi = oi; }
            }
            if(lane == 0) cand[k] = bi;
            bi = __shfl_sync(0xffffffffu, bi, 0);
            if((bi & 31) == lane) v[bi >> 5] = -3.0e38f;
        }
    }
    __syncthreads();

    const float* mm = g_magf + (size_t)row * DD;
    double mn = g_mnorm_d[row];
    for(int c = warp; c < NCAND; c += 4){
        int idx = cand[c];
        const float* cm = g_cmagf + (size_t)idx * DD;
        double acc = 0.0;
        for(int d = lane; d < DD; d += 32)
            acc = fma((double)mm[d], (double)cm[d], acc);
        #pragma unroll
        for(int off = 16; off; off >>= 1)
            acc += __shfl_xor_sync(0xffffffffu, acc, off);
        if(lane == 0)
            sval[c] = acc / (mn * g_cnorm_d[idx]);
    }
    __syncthreads();

    if(tid == 0){
        bool used[NCAND];
        #pragma unroll
        for(int i = 0; i < NCAND; i++) used[i] = false;
        for(int k = 0; k < TOPK; k++){
            int b = -1;
            for(int i = 0; i < NCAND; i++){
                if(used[i]) continue;
                if(b < 0 || sval[i] > sval[b] ||
                   (sval[i] == sval[b] && cand[i] < cand[b])) b = i;
            }
            used[b] = true;
            osims[row * TOPK + k] = (float)sval[b];
            oidx [row * TOPK + k] = (float)cand[b];
        }
    }
}

// ---------------- tiled fp16 mma GEMM, NT: C[M,N] = A[M,K] @ B[N,K]^T ----------------
// NTERMS==3: acc = A0*B0 + A1*B0 + A0*B1  (hi/lo split for ~fp32 accuracy)
// 3-stage cp.async ring -> ONE __syncthreads per mainloop iteration.
#define BN 128
#define BK 64
#define KP 72   // 144B row stride: 8-row ldmatrix offsets mod 128 = {0,16,..,112} conflict-free

struct Epi {
    float* out_f; __half* out_hi; __half* out_lo;
    const float* bias; const float* rinv; const float* cinv;
    int ldo; int nreal;
};

template<int NTERMS, int BMv, int NTHR>
__device__ __forceinline__ void load_tiles(const __half* __restrict__ A0, const __half* __restrict__ A1,
                                           const __half* __restrict__ B0, const __half* __restrict__ B1,
                                           int K, int kTiles, int it, int bm, int bn, int tid,
                                           __half* stg)
{
    int t  = it / kTiles;
    int kk = (it - t * kTiles) * BK;
    const __half* A  = (NTERMS == 3 && t == 1) ? A1 : A0;
    const __half* Bp = (NTERMS == 3 && t == 2) ? B1 : B0;
    __half* sA = stg;
    __half* sB = stg + BMv * KP;
    const int CH = (BMv + BN) * 8 / NTHR;   // 16B chunks per thread
    #pragma unroll
    for(int r = 0; r < CH; r++){
        int id  = tid + r * NTHR;
        int row = id >> 3, c = id & 7;
        if(row < BMv){
            CP_ASYNC(cvta_s(sA + row * KP + c * 8),
                     A  + (size_t)(bm * BMv + row) * K + kk + c * 8);
        } else {
            CP_ASYNC(cvta_s(sB + (row - BMv) * KP + c * 8),
                     Bp + (size_t)(bn * BN + (row - BMv)) * K + kk + c * 8);
        }
    }
    CP_COMMIT;
}

// ---- 8-warp kernel (warp tile (MT*16) x 32) for small layers ----
template<int MODE, int NTERMS, int SWAPG, int MT>
__global__ void __launch_bounds__(256, 2) gemm_nt(
    const __half* __restrict__ A0, const __half* __restrict__ A1,
    const __half* __restrict__ B0, const __half* __restrict__ B1,
    int K, Epi ep)
{
    const int BMv = MT * 32;
    const int STG = (BMv + BN) * KP;
    extern __shared__ __half sm[];

    const int tid = threadIdx.x;
    const int bn = SWAPG ? blockIdx.y : blockIdx.x;
    const int bm = SWAPG ? blockIdx.x : blockIdx.y;
    const int lane = tid & 31, warp = tid >> 5;
    const int wm = warp >> 2, wn = warp & 3;   // 2 x 4 warps

    const int kTiles = K / BK;
    const int total  = NTERMS * kTiles;

    float acc[MT][4][4];
    #pragma unroll
    for(int a = 0; a < MT; a++)
        #pragma unroll
        for(int b = 0; b < 4; b++)
            #pragma unroll
            for(int e = 0; e < 4; e++) acc[a][b][e] = 0.f;

    load_tiles<NTERMS, BMv, 256>(A0, A1, B0, B1, K, kTiles, 0, bm, bn, tid, sm);
    load_tiles<NTERMS, BMv, 256>(A0, A1, B0, B1, K, kTiles, 1, bm, bn, tid, sm + STG);

    for(int i = 0; i < total; i++){
        if(i < total - 1) CP_WAIT1; else CP_WAIT0;
        __syncthreads();
        if(i + 2 < total){
            int s = (i + 2) % 3;
            load_tiles<NTERMS, BMv, 256>(A0, A1, B0, B1, K, kTiles, i + 2, bm, bn, tid,
                                         sm + s * STG);
        }
        const __half* cA = sm + (i % 3) * STG;
        const __half* cB = cA + BMv * KP;
        #pragma unroll
        for(int ks = 0; ks < 4; ks++){
            uint32_t a[MT][4], b[4][2];
            #pragma unroll
            for(int mi = 0; mi < MT; mi++){
                int row = wm * (MT * 16) + mi * 16 + (lane & 15);
                int col = ks * 16 + ((lane >> 4) & 1) * 8;
                uint32_t addr = cvta_s(cA + row * KP + col);
                asm volatile("ldmatrix.sync.aligned.m8n8.x4.shared.b16 {%0,%1,%2,%3},[%4];\n"
                    : "=r"(a[mi][0]), "=r"(a[mi][1]), "=r"(a[mi][2]), "=r"(a[mi][3]) : "r"(addr));
            }
            #pragma unroll
            for(int ni = 0; ni < 2; ni++){
                int row = wn * 32 + ni * 16 + (lane & 7) + ((lane >> 4) & 1) * 8;
                int col = ks * 16 + ((lane >> 3) & 1) * 8;
                uint32_t addr = cvta_s(cB + row * KP + col);
                uint32_t r0, r1, r2, r3;
                asm volatile("ldmatrix.sync.aligned.m8n8.x4.shared.b16 {%0,%1,%2,%3},[%4];\n"
                    : "=r"(r0), "=r"(r1), "=r"(r2), "=r"(r3) : "r"(addr));
                b[ni * 2][0] = r0; b[ni * 2][1] = r1;
                b[ni * 2 + 1][0] = r2; b[ni * 2 + 1][1] = r3;
            }
            #pragma unroll
            for(int mi = 0; mi < MT; mi++)
                #pragma unroll
                for(int nj = 0; nj < 4; nj++)
                    asm volatile("mma.sync.aligned.m16n8k16.row.col.f32.f16.f16.f32 "
                        "{%0,%1,%2,%3},{%4,%5,%6,%7},{%8,%9},{%0,%1,%2,%3};\n"
                        : "+f"(acc[mi][nj][0]), "+f"(acc[mi][nj][1]),
                          "+f"(acc[mi][nj][2]), "+f"(acc[mi][nj][3])
                        : "r"(a[mi][0]), "r"(a[mi][1]), "r"(a[mi][2]), "r"(a[mi][3]),
                          "r"(b[nj][0]), "r"(b[nj][1]));
        }
    }

    // epilogue
    const int groupID = lane >> 2, tid4 = lane & 3;
    #pragma unroll
    for(int mi = 0; mi < MT; mi++){
        #pragma unroll
        for(int nj = 0; nj < 4; nj++){
            #pragma unroll
            for(int e = 0; e < 4; e++){
                int r = bm * BMv + wm * (MT * 16) + mi * 16 + groupID + ((e >= 2) ? 8 : 0);
                int c = bn * BN + wn * 32 + nj * 8 + tid4 * 2 + (e & 1);
                float v = acc[mi][nj][e];
                if(MODE == 0){                 // sims: scale by row/col reciprocal norms
                    ep.out_f[(size_t)r * ep.ldo + c] = v * ep.rinv[r] * ep.cinv[c];
                } else if(MODE == 1){          // gelu, store hi/lo split
                    v = gelu_f(v + ep.bias[c]);
                    __half h = __float2half(v);
                    ep.out_hi[(size_t)r * ep.ldo + c] = h;
                    ep.out_lo[(size_t)r * ep.ldo + c] = __float2half(v - __half2float(h));
                } else if(MODE == 2){          // gelu, store single half
                    v = gelu_f(v + ep.bias[c]);
                    ep.out_hi[(size_t)r * ep.ldo + c] = __float2half(v);
                }
            }
        }
    }
}

// ---- 4-warp L4 kernel: 128 threads, warp tile 64x64, CTA tile 128x128 ----
// Halves per-FLOP ldmatrix smem traffic vs the 8-warp 64x32 layout (8 LDSM.x4 / 32 mma).
__global__ void __launch_bounds__(128, 2) gemm_l4(
    const __half* __restrict__ A, const __half* __restrict__ B,
    int K, float* __restrict__ out, const float* __restrict__ bias, int nreal)
{
    const int BMv = 128;
    const int STG = (BMv + BN) * KP;
    extern __shared__ __half sm[];

    const int tid = threadIdx.x;
    const int bn = blockIdx.y, bm = blockIdx.x;   // bm fastest -> W4t tile L2 reuse
    const int lane = tid & 31, warp = tid >> 5;
    const int wm = warp >> 1, wn = warp & 1;      // 2 x 2 warps, warp tile 64x64

    const int total = K / BK;

    float acc[4][8][4];
    #pragma unroll
    for(int a = 0; a < 4; a++)
        #pragma unroll
        for(int b = 0; b < 8; b++)
            #pragma unroll
            for(int e = 0; e < 4; e++) acc[a][b][e] = 0.f;

    load_tiles<1, BMv, 128>(A, nullptr, B, nullptr, K, total, 0, bm, bn, tid, sm);
    load_tiles<1, BMv, 128>(A, nullptr, B, nullptr, K, total, 1, bm, bn, tid, sm + STG);

    for(int i = 0; i < total; i++){
        if(i < total - 1) CP_WAIT1; else CP_WAIT0;
        __syncthreads();
        if(i + 2 < total){
            int s = (i + 2) % 3;
            load_tiles<1, BMv, 128>(A, nullptr, B, nullptr, K, total, i + 2, bm, bn, tid,
                                    sm + s * STG);
        }
        const __half* cA = sm + (i % 3) * STG;
        const __half* cB = cA + BMv * KP;
        #pragma unroll
        for(int ks = 0; ks < 4; ks++){
            uint32_t a[4][4], b[8][2];
            #pragma unroll
            for(int mi = 0; mi < 4; mi++){
                int row = wm * 64 + mi * 16 + (lane & 15);
                int col = ks * 16 + ((lane >> 4) & 1) * 8;
                uint32_t addr = cvta_s(cA + row * KP + col);
                asm volatile("ldmatrix.sync.aligned.m8n8.x4.shared.b16 {%0,%1,%2,%3},[%4];\n"
                    : "=r"(a[mi][0]), "=r"(a[mi][1]), "=r"(a[mi][2]), "=r"(a[mi][3]) : "r"(addr));
            }
            #pragma unroll
            for(int ni = 0; ni < 4; ni++){
                int row = wn * 64 + ni * 16 + (lane & 7) + ((lane >> 4) & 1) * 8;
                int col = ks * 16 + ((lane >> 3) & 1) * 8;
                uint32_t addr = cvta_s(cB + row * KP + col);
                uint32_t r0, r1, r2, r3;
                asm volatile("ldmatrix.sync.aligned.m8n8.x4.shared.b16 {%0,%1,%2,%3},[%4];\n"
                    : "=r"(r0), "=r"(r1), "=r"(r2), "=r"(r3) : "r"(addr));
                b[ni * 2][0] = r0; b[ni * 2][1] = r1;
                b[ni * 2 + 1][0] = r2; b[ni * 2 + 1][1] = r3;
            }
            #pragma unroll
            for(int mi = 0; mi < 4; mi++)
                #pragma unroll
                for(int nj = 0; nj < 8; nj++)
                    asm volatile("mma.sync.aligned.m16n8k16.row.col.f32.f16.f16.f32 "
                        "{%0,%1,%2,%3},{%4,%5,%6,%7},{%8,%9},{%0,%1,%2,%3};\n"
                        : "+f"(acc[mi][nj][0]), "+f"(acc[mi][nj][1]),
                          "+f"(acc[mi][nj][2]), "+f"(acc[mi][nj][3])
                        : "r"(a[mi][0]), "r"(a[mi][1]), "r"(a[mi][2]), "r"(a[mi][3]),
                          "r"(b[nj][0]), "r"(b[nj][1]));
        }
    }

    // epilogue: bias + fp32 float2 stores, guarded by nreal
    const int groupID = lane >> 2, tid4 = lane & 3;
    #pragma unroll
    for(int mi = 0; mi < 4; mi++){
        #pragma unroll
        for(int nj = 0; nj < 8; nj++){
            int r0 = bm * BMv + wm * 64 + mi * 16 + groupID;
            int c  = bn * BN + wn * 64 + nj * 8 + tid4 * 2;
            if(c < nreal){
                float bc0 = bias[c], bc1 = bias[c + 1];
                float2 v0 = make_float2(acc[mi][nj][0] + bc0, acc[mi][nj][1] + bc1);
                float2 v1 = make_float2(acc[mi][nj][2] + bc0, acc[mi][nj][3] + bc1);
                *(float2*)&out[(size_t)r0 * nreal + c]       = v0;
                *(float2*)&out[(size_t)(r0 + 8) * nreal + c] = v1;
            }
        }
    }
}

// ---------------- launch ----------------
extern "C" void kernel_launch(void* const* d_in, const int* in_sizes, int n_in,
                              void* d_out, int out_size)
{
    const float* sre = (const float*)d_in[0];
    const float* simg= (const float*)d_in[1];
    const float* cre = (const float*)d_in[2];
    const float* cim = (const float*)d_in[3];
    const float* W1  = (const float*)d_in[4];
    const float* b1  = (const float*)d_in[5];
    const float* W2  = (const float*)d_in[6];
    const float* b2  = (const float*)d_in[7];
    const float* W3  = (const float*)d_in[8];
    const float* b3  = (const float*)d_in[9];
    const float* W4  = (const float*)d_in[10];
    const float* b4  = (const float*)d_in[11];

    __half *xhi,*xlo,*mhi,*chi,*w1hi,*w1lo,*w2hi,*w2lo,*w3hi,*w3lo,*w4t;
    __half *h1hi,*h1lo,*h2hi,*h2lo,*h3;
    float *minv,*cinv,*simsb;
    cudaGetSymbolAddress((void**)&xhi,  g_xhi);  cudaGetSymbolAddress((void**)&xlo,  g_xlo);
    cudaGetSymbolAddress((void**)&mhi,  g_mhi);  cudaGetSymbolAddress((void**)&chi,  g_chi);
    cudaGetSymbolAddress((void**)&w1hi, g_w1hi); cudaGetSymbolAddress((void**)&w1lo, g_w1lo);
    cudaGetSymbolAddress((void**)&w2hi, g_w2hi); cudaGetSymbolAddress((void**)&w2lo, g_w2lo);
    cudaGetSymbolAddress((void**)&w3hi, g_w3hi); cudaGetSymbolAddress((void**)&w3lo, g_w3lo);
    cudaGetSymbolAddress((void**)&w4t,  g_w4t);
    cudaGetSymbolAddress((void**)&h1hi, g_h1hi); cudaGetSymbolAddress((void**)&h1lo, g_h1lo);
    cudaGetSymbolAddress((void**)&h2hi, g_h2hi); cudaGetSymbolAddress((void**)&h2lo, g_h2lo);
    cudaGetSymbolAddress((void**)&h3,   g_h3);
    cudaGetSymbolAddress((void**)&minv, g_minv); cudaGetSymbolAddress((void**)&cinv, g_cinv);
    cudaGetSymbolAddress((void**)&simsb,g_sims);

    float* out        = (float*)d_out;
    float* out_sims   = out;
    float* out_idx    = out + (size_t)HM * TOPK;
    float* out_logits = out + (size_t)2 * HM * TOPK;
    if(out_size == (int)((size_t)HM * NV)){   // logits-only layout fallback
        out_logits = out; out_sims = nullptr; out_idx = nullptr;
    }

    const int SM_SMALL = 3 * (64  + BN) * KP * (int)sizeof(__half);   // 82944
    const int SM_BIG   = 3 * (128 + BN) * KP * (int)sizeof(__half);   // 110592

    // one-time setup on the FIRST (uncaptured) correctness call
    static cudaStream_t s1 = 0;
    static cudaEvent_t evFork = 0, evW23 = 0, evW4 = 0, evX = 0, evS = 0;
    if(!s1){
        cudaFuncSetAttribute(gemm_nt<0,1,0,2>, cudaFuncAttributeMaxDynamicSharedMemorySize, SM_SMALL);
        cudaFuncSetAttribute(gemm_nt<1,3,0,2>, cudaFuncAttributeMaxDynamicSharedMemorySize, SM_SMALL);
        cudaFuncSetAttribute(gemm_nt<2,3,0,2>, cudaFuncAttributeMaxDynamicSharedMemorySize, SM_SMALL);
        cudaFuncSetAttribute(gemm_l4,          cudaFuncAttributeMaxDynamicSharedMemorySize, SM_BIG);
        cudaStreamCreateWithFlags(&s1, cudaStreamNonBlocking);
        cudaEventCreateWithFlags(&evFork, cudaEventDisableTiming);
        cudaEventCreateWithFlags(&evW23,  cudaEventDisableTiming);
        cudaEventCreateWithFlags(&evW4,   cudaEventDisableTiming);
        cudaEventCreateWithFlags(&evX,    cudaEventDisableTiming);
        cudaEventCreateWithFlags(&evS,    cudaEventDisableTiming);
    }

    dim3 tb(32, 8);
    Epi e;

    // ---- fork side stream ----
    cudaEventRecord(evFork, 0);
    cudaStreamWaitEvent(s1, evFork, 0);

    // ---- s1: prep_c + W2/W3 then W4 ----
    prep_c_kernel<<<NCP, 256, 0, s1>>>(cre, cim);
    wconv_kernel<<<dim3(512/32, DD/32), tb, 0, s1>>>(W2, w2hi, w2lo, DD,  512, 512);
    wconv_kernel<<<dim3(DD/32,  512/32),tb, 0, s1>>>(W3, w3hi, w3lo, 512, DD,  DD);
    cudaEventRecord(evW23, s1);
    wconv_kernel<<<dim3(NVP/32, DD/32), tb, 0, s1>>>(W4, w4t, nullptr, DD, NV, NVP);
    cudaEventRecord(evW4, s1);

    // ---- s0 (main): W1 + input prep ----
    wconv_kernel<<<dim3(DD/32,  K1/32), tb>>>(W1, w1hi, w1lo, K1,  DD,  DD);
    prep_x_kernel<<<HM, 256>>>(sre, simg);
    cudaEventRecord(evX, 0);
    cudaStreamWaitEvent(s1, evX, 0);

    // ---- s1: sims filter (single-term fp16) + topk rescore ----
    if(out_sims){
        e = Epi{}; e.out_f = simsb; e.rinv = minv; e.cinv = cinv; e.ldo = NCP;
        gemm_nt<0,1,0,2><<<dim3(NCP/BN, HM/64), 256, SM_SMALL, s1>>>(mhi, nullptr, chi, nullptr, DD, e);
        topk_rescore<<<HM, 128, 0, s1>>>(out_sims, out_idx);
    }
    cudaEventRecord(evS, s1);

    // ---- s0: L1 (needs only W1 + prep_x) ----
    e = Epi{}; e.out_hi = h1hi; e.out_lo = h1lo; e.bias = b1; e.ldo = DD;
    gemm_nt<1,3,0,2><<<dim3(DD/BN, HM/64), 256, SM_SMALL>>>(xhi, xlo, w1hi, w1lo, K1, e);

    cudaStreamWaitEvent(0, evW23, 0);
    e = Epi{}; e.out_hi = h2hi; e.out_lo = h2lo; e.bias = b2; e.ldo = 512;
    gemm_nt<1,3,0,2><<<dim3(512/BN, HM/64), 256, SM_SMALL>>>(h1hi, h1lo, w2hi, w2lo, DD, e);
    e = Epi{}; e.out_hi = h3; e.bias = b3; e.ldo = DD;
    gemm_nt<2,3,0,2><<<dim3(DD/BN, HM/64), 256, SM_SMALL>>>(h2hi, h2lo, w3hi, w3lo, 512, e);

    cudaStreamWaitEvent(0, evW4, 0);
    gemm_l4<<<dim3(HM/128, NVP/BN), 128, SM_BIG>>>(h3, w4t, DD, out_logits, b4, NV);

    // ---- join ----
    cudaStreamWaitEvent(0, evS, 0);
}

// round 13
// speedup vs baseline: 1.0344x; 1.0344x over previous
#include <cuda_runtime.h>
#include <cuda_fp16.h>
#include <math.h>
#include <stdint.h>

// ---------------- problem constants ----------------
#define HM   2048      // B*S = 4*512 rows
#define DD   768       // feature dim
#define K1   1536      // 2*D (concat real/imag)
#define NC   1000      // concepts
#define NCP  1024      // padded
#define NV   50000     // vocab
#define NVP  50176     // padded (392 tiles of 128)
#define TOPK 5
#define NCAND 32       // rescore candidate count (single-term fp16 filter -> wide net)

// ---------------- scratch (static device allocs are legal) ----------------
__device__ __align__(256) __half g_xhi[HM*K1];
__device__ __align__(256) __half g_xlo[HM*K1];
__device__ __align__(256) __half g_mhi[HM*DD];
__device__ __align__(256) float  g_minv[HM];
__device__ __align__(256) __half g_chi[NCP*DD];
__device__ __align__(256) float  g_cinv[NCP];
__device__ __align__(256) __half g_w1hi[DD*K1];
__device__ __align__(256) __half g_w1lo[DD*K1];
__device__ __align__(256) __half g_w2hi[512*DD];
__device__ __align__(256) __half g_w2lo[512*DD];
__device__ __align__(256) __half g_w3hi[DD*512];
__device__ __align__(256) __half g_w3lo[DD*512];
__device__ __align__(256) __half g_w4t[(size_t)NVP*DD];
__device__ __align__(256) float  g_sims[(size_t)HM*NCP];
__device__ __align__(256) __half g_h1hi[HM*DD];
__device__ __align__(256) __half g_h1lo[HM*DD];
__device__ __align__(256) __half g_h2hi[HM*512];
__device__ __align__(256) __half g_h2lo[HM*512];
__device__ __align__(256) __half g_h3[HM*DD];
// exact-path buffers for fp64 rescoring
__device__ __align__(256) float  g_magf [HM*DD];
__device__ __align__(256) float  g_cmagf[NC*DD];
__device__ __align__(256) double g_mnorm_d[HM];
__device__ __align__(256) double g_cnorm_d[NCP];

// ---------------- helpers ----------------
__device__ __forceinline__ uint32_t cvta_s(const void* p){
    return (uint32_t)__cvta_generic_to_shared(p);
}
#define CP_ASYNC(dst, src) asm volatile("cp.async.cg.shared.global [%0], [%1], 16;\n" :: "r"(dst), "l"(src))
#define CP_COMMIT          asm volatile("cp.async.commit_group;\n" ::)
#define CP_WAIT1           asm volatile("cp.async.wait_group 1;\n" ::)
#define CP_WAIT0           asm volatile("cp.async.wait_group 0;\n" ::)

__device__ __forceinline__ float gelu_f(float x){
    return 0.5f * x * (1.0f + erff(x * 0.7071067811865475f));
}

// reference-matching fp32 magnitude: r*r, i*i, add, sqrt — all RN, NO fma contraction
__device__ __forceinline__ float mag_ref(float r, float i){
    return __fsqrt_rn(__fadd_rn(__fmul_rn(r, r), __fmul_rn(i, i)));
}

// ---------------- prep kernels ----------------
// transpose + fp32 -> fp16 hi/lo split:  W[K,N] row-major  ->  Wt[Npad,K]
__global__ void wconv_kernel(const float* __restrict__ W, __half* __restrict__ outHi,
                             __half* __restrict__ outLo, int K, int N, int Npad)
{
    __shared__ float tile[32][33];
    int k0 = blockIdx.y * 32, n0 = blockIdx.x * 32;
    int tx = threadIdx.x, ty = threadIdx.y;
    #pragma unroll
    for(int i = 0; i < 32; i += 8){
        int k = k0 + ty + i, n = n0 + tx;
        tile[ty + i][tx] = (n < N) ? W[(size_t)k * N + n] : 0.f;
    }
    __syncthreads();
    #pragma unroll
    for(int i = 0; i < 32; i += 8){
        int n = n0 + ty + i, k = k0 + tx;
        if(n < Npad){
            float v = tile[tx][ty + i];
            __half h = __float2half(v);
            outHi[(size_t)n * K + k] = h;
            if(outLo) outLo[(size_t)n * K + k] = __float2half(v - __half2float(h));
        }
    }
}

// per-row: x = [re, im] hi/lo split; mag (ref-exact fp32) fp16 + fp32 copy; fp64 norm
__global__ void prep_x_kernel(const float* __restrict__ re, const float* __restrict__ im)
{
    int row = blockIdx.x, tid = threadIdx.x;
    __shared__ double red[256];
    double ss = 0.0;
    for(int d = tid; d < DD; d += 256){
        float r  = re[(size_t)row * DD + d];
        float ii = im[(size_t)row * DD + d];
        __half hr = __float2half(r);
        __half hi2 = __float2half(ii);
        g_xhi[(size_t)row * K1 + d]      = hr;
        g_xlo[(size_t)row * K1 + d]      = __float2half(r - __half2float(hr));
        g_xhi[(size_t)row * K1 + DD + d] = hi2;
        g_xlo[(size_t)row * K1 + DD + d] = __float2half(ii - __half2float(hi2));
        float m = mag_ref(r, ii);
        g_magf[(size_t)row * DD + d] = m;
        ss = fma((double)m, (double)m, ss);
        g_mhi[(size_t)row * DD + d] = __float2half(m);
    }
    red[tid] = ss; __syncthreads();
    for(int s = 128; s > 0; s >>= 1){ if(tid < s) red[tid] += red[tid + s]; __syncthreads(); }
    if(tid == 0){
        double n = sqrt(red[0]);
        if(n < 1e-8) n = 1e-8;
        g_mnorm_d[row] = n;
        g_minv[row] = (float)(1.0 / n);
    }
}

__global__ void prep_c_kernel(const float* __restrict__ cre, const float* __restrict__ cim)
{
    int row = blockIdx.x, tid = threadIdx.x;
    __shared__ double red[256];
    double ss = 0.0;
    for(int d = tid; d < DD; d += 256){
        float m = 0.f;
        if(row < NC){
            float r = cre[(size_t)row * DD + d];
            float ii = cim[(size_t)row * DD + d];
            m = mag_ref(r, ii);
            g_cmagf[(size_t)row * DD + d] = m;
        }
        ss = fma((double)m, (double)m, ss);
        g_chi[(size_t)row * DD + d] = __float2half(m);
    }
    red[tid] = ss; __syncthreads();
    for(int s = 128; s > 0; s >>= 1){ if(tid < s) red[tid] += red[tid + s]; __syncthreads(); }
    if(tid == 0){
        double n = sqrt(red[0]);
        if(n < 1e-8) n = 1e-8;
        g_cnorm_d[row] = n;
        g_cinv[row] = (float)(1.0 / n);
    }
}

// ---------------- top-k: candidate filter (approx sims) + fp64 rescore ----------------
__global__ void topk_rescore(float* __restrict__ osims, float* __restrict__ oidx)
{
    int row = blockIdx.x;
    int tid = threadIdx.x, lane = tid & 31, warp = tid >> 5;
    __shared__ int    cand[NCAND];
    __shared__ double sval[NCAND];

    if(warp == 0){
        const float* s = g_sims + (size_t)row * NCP;
        float v[32];
        #pragma unroll
        for(int j = 0; j < 32; j++){
            int idx = j * 32 + lane;
            v[j] = (idx < NC) ? s[idx] : -3.0e38f;
        }
        for(int k = 0; k < NCAND; k++){
            float best = -3.0e38f; int bi = 1 << 20;
            #pragma unroll
            for(int j = 0; j < 32; j++){
                int idx = j * 32 + lane;
                if(v[j] > best){ best = v[j]; bi = idx; }
            }
            #pragma unroll
            for(int off = 16; off; off >>= 1){
                float ov = __shfl_xor_sync(0xffffffffu, best, off);
                int   oi = __shfl_xor_sync(0xffffffffu, bi,   off);
                if(ov > best || (ov == best && oi < bi)){ best = ov; bi = oi; }
            }
            if(lane == 0) cand[k] = bi;
            bi = __shfl_sync(0xffffffffu, bi, 0);
            if((bi & 31) == lane) v[bi >> 5] = -3.0e38f;
        }
    }
    __syncthreads();

    const float* mm = g_magf + (size_t)row * DD;
    double mn = g_mnorm_d[row];
    for(int c = warp; c < NCAND; c += 4){
        int idx = cand[c];
        const float* cm = g_cmagf + (size_t)idx * DD;
        double acc = 0.0;
        for(int d = lane; d < DD; d += 32)
            acc = fma((double)mm[d], (double)cm[d], acc);
        #pragma unroll
        for(int off = 16; off; off >>= 1)
            acc += __shfl_xor_sync(0xffffffffu, acc, off);
        if(lane == 0)
            sval[c] = acc / (mn * g_cnorm_d[idx]);
    }
    __syncthreads();

    if(tid == 0){
        bool used[NCAND];
        #pragma unroll
        for(int i = 0; i < NCAND; i++) used[i] = false;
        for(int k = 0; k < TOPK; k++){
            int b = -1;
            for(int i = 0; i < NCAND; i++){
                if(used[i]) continue;
                if(b < 0 || sval[i] > sval[b] ||
                   (sval[i] == sval[b] && cand[i] < cand[b])) b = i;
            }
            used[b] = true;
            osims[row * TOPK + k] = (float)sval[b];
            oidx [row * TOPK + k] = (float)cand[b];
        }
    }
}

// ---------------- tiled fp16 mma GEMM, NT: C[M,N] = A[M,K] @ B[N,K]^T ----------------
// NTERMS==3: acc = A0*B0 + A1*B0 + A0*B1  (hi/lo split for ~fp32 accuracy)
// 3-stage cp.async ring -> ONE __syncthreads per mainloop iteration.
// 8 warps (2 wm x 4 wn), warp tile (MT*16) x 32 — proven best HMMA operating point.
#define BN 128
#define BK 64
#define KP 72   // 144B row stride: 8-row ldmatrix offsets mod 128 = {0,16,..,112} conflict-free

struct Epi {
    float* out_f; __half* out_hi; __half* out_lo;
    const float* bias; const float* rinv; const float* cinv;
    int ldo; int nreal;
};

template<int NTERMS, int BMv>
__device__ __forceinline__ void load_tiles(const __half* __restrict__ A0, const __half* __restrict__ A1,
                                           const __half* __restrict__ B0, const __half* __restrict__ B1,
                                           int K, int kTiles, int it, int bm, int bn, int tid,
                                           __half* stg)
{
    int t  = it / kTiles;
    int kk = (it - t * kTiles) * BK;
    const __half* A  = (NTERMS == 3 && t == 1) ? A1 : A0;
    const __half* Bp = (NTERMS == 3 && t == 2) ? B1 : B0;
    __half* sA = stg;
    __half* sB = stg + BMv * KP;
    const int CH = (BMv + BN) * 8 / 256;   // 16B chunks per thread
    #pragma unroll
    for(int r = 0; r < CH; r++){
        int id  = tid + r * 256;
        int row = id >> 3, c = id & 7;
        if(row < BMv){
            CP_ASYNC(cvta_s(sA + row * KP + c * 8),
                     A  + (size_t)(bm * BMv + row) * K + kk + c * 8);
        } else {
            CP_ASYNC(cvta_s(sB + (row - BMv) * KP + c * 8),
                     Bp + (size_t)(bn * BN + (row - BMv)) * K + kk + c * 8);
        }
    }
    CP_COMMIT;
}

template<int MODE, int NTERMS, int SWAPG, int MT>
__global__ void __launch_bounds__(256, 2) gemm_nt(
    const __half* __restrict__ A0, const __half* __restrict__ A1,
    const __half* __restrict__ B0, const __half* __restrict__ B1,
    int K, Epi ep)
{
    const int BMv = MT * 32;
    const int STG = (BMv + BN) * KP;
    extern __shared__ __half sm[];

    const int tid = threadIdx.x;
    const int bn = SWAPG ? blockIdx.y : blockIdx.x;
    const int bm = SWAPG ? blockIdx.x : blockIdx.y;
    const int lane = tid & 31, warp = tid >> 5;
    const int wm = warp >> 2, wn = warp & 3;   // 2 x 4 warps

    const int kTiles = K / BK;
    const int total  = NTERMS * kTiles;

    float acc[MT][4][4];
    #pragma unroll
    for(int a = 0; a < MT; a++)
        #pragma unroll
        for(int b = 0; b < 4; b++)
            #pragma unroll
            for(int e = 0; e < 4; e++) acc[a][b][e] = 0.f;

    load_tiles<NTERMS, BMv>(A0, A1, B0, B1, K, kTiles, 0, bm, bn, tid, sm);
    load_tiles<NTERMS, BMv>(A0, A1, B0, B1, K, kTiles, 1, bm, bn, tid, sm + STG);

    for(int i = 0; i < total; i++){
        if(i < total - 1) CP_WAIT1; else CP_WAIT0;
        __syncthreads();
        if(i + 2 < total){
            int s = (i + 2) % 3;
            load_tiles<NTERMS, BMv>(A0, A1, B0, B1, K, kTiles, i + 2, bm, bn, tid,
                                    sm + s * STG);
        }
        const __half* cA = sm + (i % 3) * STG;
        const __half* cB = cA + BMv * KP;
        #pragma unroll
        for(int ks = 0; ks < 4; ks++){
            uint32_t a[MT][4], b[4][2];
            #pragma unroll
            for(int mi = 0; mi < MT; mi++){
                int row = wm * (MT * 16) + mi * 16 + (lane & 15);
                int col = ks * 16 + ((lane >> 4) & 1) * 8;
                uint32_t addr = cvta_s(cA + row * KP + col);
                asm volatile("ldmatrix.sync.aligned.m8n8.x4.shared.b16 {%0,%1,%2,%3},[%4];\n"
                    : "=r"(a[mi][0]), "=r"(a[mi][1]), "=r"(a[mi][2]), "=r"(a[mi][3]) : "r"(addr));
            }
            #pragma unroll
            for(int ni = 0; ni < 2; ni++){
                int row = wn * 32 + ni * 16 + (lane & 7) + ((lane >> 4) & 1) * 8;
                int col = ks * 16 + ((lane >> 3) & 1) * 8;
                uint32_t addr = cvta_s(cB + row * KP + col);
                uint32_t r0, r1, r2, r3;
                asm volatile("ldmatrix.sync.aligned.m8n8.x4.shared.b16 {%0,%1,%2,%3},[%4];\n"
                    : "=r"(r0), "=r"(r1), "=r"(r2), "=r"(r3) : "r"(addr));
                b[ni * 2][0] = r0; b[ni * 2][1] = r1;
                b[ni * 2 + 1][0] = r2; b[ni * 2 + 1][1] = r3;
            }
            #pragma unroll
            for(int mi = 0; mi < MT; mi++)
                #pragma unroll
                for(int nj = 0; nj < 4; nj++)
                    asm volatile("mma.sync.aligned.m16n8k16.row.col.f32.f16.f16.f32 "
                        "{%0,%1,%2,%3},{%4,%5,%6,%7},{%8,%9},{%0,%1,%2,%3};\n"
                        : "+f"(acc[mi][nj][0]), "+f"(acc[mi][nj][1]),
                          "+f"(acc[mi][nj][2]), "+f"(acc[mi][nj][3])
                        : "r"(a[mi][0]), "r"(a[mi][1]), "r"(a[mi][2]), "r"(a[mi][3]),
                          "r"(b[nj][0]), "r"(b[nj][1]));
        }
    }

    // epilogue
    const int groupID = lane >> 2, tid4 = lane & 3;
    #pragma unroll
    for(int mi = 0; mi < MT; mi++){
        #pragma unroll
        for(int nj = 0; nj < 4; nj++){
            if(MODE == 3){
                int r0 = bm * BMv + wm * (MT * 16) + mi * 16 + groupID;
                int c  = bn * BN + wn * 32 + nj * 8 + tid4 * 2;
                if(c < ep.nreal){
                    float bc0 = ep.bias[c], bc1 = ep.bias[c + 1];
                    float2 v0 = make_float2(acc[mi][nj][0] + bc0, acc[mi][nj][1] + bc1);
                    float2 v1 = make_float2(acc[mi][nj][2] + bc0, acc[mi][nj][3] + bc1);
                    *(float2*)&ep.out_f[(size_t)r0 * ep.nreal + c]       = v0;
                    *(float2*)&ep.out_f[(size_t)(r0 + 8) * ep.nreal + c] = v1;
                }
            } else {
                #pragma unroll
                for(int e = 0; e < 4; e++){
                    int r = bm * BMv + wm * (MT * 16) + mi * 16 + groupID + ((e >= 2) ? 8 : 0);
                    int c = bn * BN + wn * 32 + nj * 8 + tid4 * 2 + (e & 1);
                    float v = acc[mi][nj][e];
                    if(MODE == 0){                 // sims: scale by row/col reciprocal norms
                        ep.out_f[(size_t)r * ep.ldo + c] = v * ep.rinv[r] * ep.cinv[c];
                    } else if(MODE == 1){          // gelu, store hi/lo split
                        v = gelu_f(v + ep.bias[c]);
                        __half h = __float2half(v);
                        ep.out_hi[(size_t)r * ep.ldo + c] = h;
                        ep.out_lo[(size_t)r * ep.ldo + c] = __float2half(v - __half2float(h));
                    } else if(MODE == 2){          // gelu, store single half
                        v = gelu_f(v + ep.bias[c]);
                        ep.out_hi[(size_t)r * ep.ldo + c] = __float2half(v);
                    }
                }
            }
        }
    }
}

// ---------------- launch ----------------
extern "C" void kernel_launch(void* const* d_in, const int* in_sizes, int n_in,
                              void* d_out, int out_size)
{
    const float* sre = (const float*)d_in[0];
    const float* simg= (const float*)d_in[1];
    const float* cre = (const float*)d_in[2];
    const float* cim = (const float*)d_in[3];
    const float* W1  = (const float*)d_in[4];
    const float* b1  = (const float*)d_in[5];
    const float* W2  = (const float*)d_in[6];
    const float* b2  = (const float*)d_in[7];
    const float* W3  = (const float*)d_in[8];
    const float* b3  = (const float*)d_in[9];
    const float* W4  = (const float*)d_in[10];
    const float* b4  = (const float*)d_in[11];

    __half *xhi,*xlo,*mhi,*chi,*w1hi,*w1lo,*w2hi,*w2lo,*w3hi,*w3lo,*w4t;
    __half *h1hi,*h1lo,*h2hi,*h2lo,*h3;
    float *minv,*cinv,*simsb;
    cudaGetSymbolAddress((void**)&xhi,  g_xhi);  cudaGetSymbolAddress((void**)&xlo,  g_xlo);
    cudaGetSymbolAddress((void**)&mhi,  g_mhi);  cudaGetSymbolAddress((void**)&chi,  g_chi);
    cudaGetSymbolAddress((void**)&w1hi, g_w1hi); cudaGetSymbolAddress((void**)&w1lo, g_w1lo);
    cudaGetSymbolAddress((void**)&w2hi, g_w2hi); cudaGetSymbolAddress((void**)&w2lo, g_w2lo);
    cudaGetSymbolAddress((void**)&w3hi, g_w3hi); cudaGetSymbolAddress((void**)&w3lo, g_w3lo);
    cudaGetSymbolAddress((void**)&w4t,  g_w4t);
    cudaGetSymbolAddress((void**)&h1hi, g_h1hi); cudaGetSymbolAddress((void**)&h1lo, g_h1lo);
    cudaGetSymbolAddress((void**)&h2hi, g_h2hi); cudaGetSymbolAddress((void**)&h2lo, g_h2lo);
    cudaGetSymbolAddress((void**)&h3,   g_h3);
    cudaGetSymbolAddress((void**)&minv, g_minv); cudaGetSymbolAddress((void**)&cinv, g_cinv);
    cudaGetSymbolAddress((void**)&simsb,g_sims);

    float* out        = (float*)d_out;
    float* out_sims   = out;
    float* out_idx    = out + (size_t)HM * TOPK;
    float* out_logits = out + (size_t)2 * HM * TOPK;
    if(out_size == (int)((size_t)HM * NV)){   // logits-only layout fallback
        out_logits = out; out_sims = nullptr; out_idx = nullptr;
    }

    const int SM_SMALL = 3 * (64  + BN) * KP * (int)sizeof(__half);   // 82944
    const int SM_BIG   = 3 * (128 + BN) * KP * (int)sizeof(__half);   // 110592

    // one-time setup on the FIRST (uncaptured) correctness call
    static cudaStream_t s1 = 0;
    static cudaEvent_t evFork = 0, evW23 = 0, evW4 = 0, evX = 0, evS = 0;
    if(!s1){
        cudaFuncSetAttribute(gemm_nt<0,1,0,2>, cudaFuncAttributeMaxDynamicSharedMemorySize, SM_SMALL);
        cudaFuncSetAttribute(gemm_nt<1,3,0,2>, cudaFuncAttributeMaxDynamicSharedMemorySize, SM_SMALL);
        cudaFuncSetAttribute(gemm_nt<2,3,0,2>, cudaFuncAttributeMaxDynamicSharedMemorySize, SM_SMALL);
        cudaFuncSetAttribute(gemm_nt<3,1,1,4>, cudaFuncAttributeMaxDynamicSharedMemorySize, SM_BIG);
        cudaStreamCreateWithFlags(&s1, cudaStreamNonBlocking);
        cudaEventCreateWithFlags(&evFork, cudaEventDisableTiming);
        cudaEventCreateWithFlags(&evW23,  cudaEventDisableTiming);
        cudaEventCreateWithFlags(&evW4,   cudaEventDisableTiming);
        cudaEventCreateWithFlags(&evX,    cudaEventDisableTiming);
        cudaEventCreateWithFlags(&evS,    cudaEventDisableTiming);
    }

    dim3 tb(32, 8);
    Epi e;

    // ---- fork side stream ----
    cudaEventRecord(evFork, 0);
    cudaStreamWaitEvent(s1, evFork, 0);

    // ---- s1: prep_c + W2/W3 then W4 ----
    prep_c_kernel<<<NCP, 256, 0, s1>>>(cre, cim);
    wconv_kernel<<<dim3(512/32, DD/32), tb, 0, s1>>>(W2, w2hi, w2lo, DD,  512, 512);
    wconv_kernel<<<dim3(DD/32,  512/32),tb, 0, s1>>>(W3, w3hi, w3lo, 512, DD,  DD);
    cudaEventRecord(evW23, s1);
    wconv_kernel<<<dim3(NVP/32, DD/32), tb, 0, s1>>>(W4, w4t, nullptr, DD, NV, NVP);
    cudaEventRecord(evW4, s1);

    // ---- s0 (main): W1 + input prep ----
    wconv_kernel<<<dim3(DD/32,  K1/32), tb>>>(W1, w1hi, w1lo, K1,  DD,  DD);
    prep_x_kernel<<<HM, 256>>>(sre, simg);
    cudaEventRecord(evX, 0);
    cudaStreamWaitEvent(s1, evX, 0);

    // ---- s1: sims filter (single-term fp16) + topk rescore ----
    if(out_sims){
        e = Epi{}; e.out_f = simsb; e.rinv = minv; e.cinv = cinv; e.ldo = NCP;
        gemm_nt<0,1,0,2><<<dim3(NCP/BN, HM/64), 256, SM_SMALL, s1>>>(mhi, nullptr, chi, nullptr, DD, e);
        topk_rescore<<<HM, 128, 0, s1>>>(out_sims, out_idx);
    }
    cudaEventRecord(evS, s1);

    // ---- s0: L1 (needs only W1 + prep_x) ----
    e = Epi{}; e.out_hi = h1hi; e.out_lo = h1lo; e.bias = b1; e.ldo = DD;
    gemm_nt<1,3,0,2><<<dim3(DD/BN, HM/64), 256, SM_SMALL>>>(xhi, xlo, w1hi, w1lo, K1, e);

    cudaStreamWaitEvent(0, evW23, 0);
    e = Epi{}; e.out_hi = h2hi; e.out_lo = h2lo; e.bias = b2; e.ldo = 512;
    gemm_nt<1,3,0,2><<<dim3(512/BN, HM/64), 256, SM_SMALL>>>(h1hi, h1lo, w2hi, w2lo, DD, e);
    e = Epi{}; e.out_hi = h3; e.bias = b3; e.ldo = DD;
    gemm_nt<2,3,0,2><<<dim3(DD/BN, HM/64), 256, SM_SMALL>>>(h2hi, h2lo, w3hi, w3lo, 512, e);

    // ---- s0: L4 — proven 8-warp MT=4 kernel, SWAPPED grid for W4t L2 reuse ----
    cudaStreamWaitEvent(0, evW4, 0);
    e = Epi{}; e.out_f = out_logits; e.bias = b4; e.nreal = NV;
    gemm_nt<3,1,1,4><<<dim3(HM/128, NVP/BN), 256, SM_BIG>>>(h3, nullptr, w4t, nullptr, DD, e);

    // ---- join ----
    cudaStreamWaitEvent(0, evS, 0);
}

// round 14
// speedup vs baseline: 1.2878x; 1.2449x over previous
#include <cuda_runtime.h>
#include <cuda_fp16.h>
#include <math.h>
#include <stdint.h>

// ---------------- problem constants ----------------
#define HM   2048      // B*S = 4*512 rows
#define DD   768       // feature dim
#define K1   1536      // 2*D (concat real/imag)
#define NC   1000      // concepts
#define NCP  1024      // padded
#define NV   50000     // vocab
#define NVP  50176     // padded (392 tiles of 128)
#define TOPK 5
#define NCAND 16       // rescore candidate count

// ---------------- scratch (static device allocs are legal) ----------------
__device__ __align__(256) __half g_xhi[HM*K1];
__device__ __align__(256) __half g_xlo[HM*K1];
__device__ __align__(256) __half g_mhi[HM*DD];
__device__ __align__(256) __half g_mlo[HM*DD];
__device__ __align__(256) float  g_minv[HM];
__device__ __align__(256) __half g_chi[NCP*DD];
__device__ __align__(256) __half g_clo[NCP*DD];
__device__ __align__(256) float  g_cinv[NCP];
__device__ __align__(256) __half g_w1hi[DD*K1];
__device__ __align__(256) __half g_w1lo[DD*K1];
__device__ __align__(256) __half g_w2hi[512*DD];
__device__ __align__(256) __half g_w2lo[512*DD];
__device__ __align__(256) __half g_w3hi[DD*512];
__device__ __align__(256) __half g_w3lo[DD*512];
__device__ __align__(256) __half g_w4t[(size_t)NVP*DD];
__device__ __align__(256) float  g_sims[(size_t)HM*NCP];
__device__ __align__(256) __half g_h1hi[HM*DD];
__device__ __align__(256) __half g_h1lo[HM*DD];
__device__ __align__(256) __half g_h2hi[HM*512];
__device__ __align__(256) __half g_h2lo[HM*512];
__device__ __align__(256) __half g_h3[HM*DD];
// exact-path buffers for fp64 rescoring
__device__ __align__(256) float  g_magf [HM*DD];
__device__ __align__(256) float  g_cmagf[NC*DD];
__device__ __align__(256) double g_mnorm_d[HM];
__device__ __align__(256) double g_cnorm_d[NCP];

// ---------------- helpers ----------------
__device__ __forceinline__ uint32_t cvta_s(const void* p){
    return (uint32_t)__cvta_generic_to_shared(p);
}
#define CP_ASYNC(dst, src) asm volatile("cp.async.cg.shared.global [%0], [%1], 16;\n" :: "r"(dst), "l"(src))
#define CP_COMMIT          asm volatile("cp.async.commit_group;\n" ::)
#define CP_WAIT1           asm volatile("cp.async.wait_group 1;\n" ::)
#define CP_WAIT0           asm volatile("cp.async.wait_group 0;\n" ::)

__device__ __forceinline__ float gelu_f(float x){
    return 0.5f * x * (1.0f + erff(x * 0.7071067811865475f));
}

// reference-matching fp32 magnitude: r*r, i*i, add, sqrt — all RN, NO fma contraction
__device__ __forceinline__ float mag_ref(float r, float i){
    return __fsqrt_rn(__fadd_rn(__fmul_rn(r, r), __fmul_rn(i, i)));
}

// ---------------- prep kernels ----------------
// transpose + fp32 -> fp16 hi/lo split:  W[K,N] row-major  ->  Wt[Npad,K]
__global__ void wconv_kernel(const float* __restrict__ W, __half* __restrict__ outHi,
                             __half* __restrict__ outLo, int K, int N, int Npad)
{
    __shared__ float tile[32][33];
    int k0 = blockIdx.y * 32, n0 = blockIdx.x * 32;
    int tx = threadIdx.x, ty = threadIdx.y;
    #pragma unroll
    for(int i = 0; i < 32; i += 8){
        int k = k0 + ty + i, n = n0 + tx;
        tile[ty + i][tx] = (n < N) ? W[(size_t)k * N + n] : 0.f;
    }
    __syncthreads();
    #pragma unroll
    for(int i = 0; i < 32; i += 8){
        int n = n0 + ty + i, k = k0 + tx;
        if(n < Npad){
            float v = tile[tx][ty + i];
            __half h = __float2half(v);
            outHi[(size_t)n * K + k] = h;
            if(outLo) outLo[(size_t)n * K + k] = __float2half(v - __half2float(h));
        }
    }
}

// per-row: x = [re, im] hi/lo split; mag (ref-exact fp32) hi/lo split + fp32 copy; fp64 norm
__global__ void prep_x_kernel(const float* __restrict__ re, const float* __restrict__ im)
{
    int row = blockIdx.x, tid = threadIdx.x;
    __shared__ double red[256];
    double ss = 0.0;
    for(int d = tid; d < DD; d += 256){
        float r  = re[(size_t)row * DD + d];
        float ii = im[(size_t)row * DD + d];
        __half hr = __float2half(r);
        __half hi2 = __float2half(ii);
        g_xhi[(size_t)row * K1 + d]      = hr;
        g_xlo[(size_t)row * K1 + d]      = __float2half(r - __half2float(hr));
        g_xhi[(size_t)row * K1 + DD + d] = hi2;
        g_xlo[(size_t)row * K1 + DD + d] = __float2half(ii - __half2float(hi2));
        float m = mag_ref(r, ii);
        g_magf[(size_t)row * DD + d] = m;
        ss = fma((double)m, (double)m, ss);
        __half hm = __float2half(m);
        g_mhi[(size_t)row * DD + d] = hm;
        g_mlo[(size_t)row * DD + d] = __float2half(m - __half2float(hm));
    }
    red[tid] = ss; __syncthreads();
    for(int s = 128; s > 0; s >>= 1){ if(tid < s) red[tid] += red[tid + s]; __syncthreads(); }
    if(tid == 0){
        double n = sqrt(red[0]);
        if(n < 1e-8) n = 1e-8;
        g_mnorm_d[row] = n;
        g_minv[row] = (float)(1.0 / n);
    }
}

__global__ void prep_c_kernel(const float* __restrict__ cre, const float* __restrict__ cim)
{
    int row = blockIdx.x, tid = threadIdx.x;
    __shared__ double red[256];
    double ss = 0.0;
    for(int d = tid; d < DD; d += 256){
        float m = 0.f;
        if(row < NC){
            float r = cre[(size_t)row * DD + d];
            float ii = cim[(size_t)row * DD + d];
            m = mag_ref(r, ii);
            g_cmagf[(size_t)row * DD + d] = m;
        }
        ss = fma((double)m, (double)m, ss);
        __half hm = __float2half(m);
        g_chi[(size_t)row * DD + d] = hm;
        g_clo[(size_t)row * DD + d] = __float2half(m - __half2float(hm));
    }
    red[tid] = ss; __syncthreads();
    for(int s = 128; s > 0; s >>= 1){ if(tid < s) red[tid] += red[tid + s]; __syncthreads(); }
    if(tid == 0){
        double n = sqrt(red[0]);
        if(n < 1e-8) n = 1e-8;
        g_cnorm_d[row] = n;
        g_cinv[row] = (float)(1.0 / n);
    }
}

// ---------------- top-k: candidate filter (approx sims) + fp64 rescore ----------------
__global__ void topk_rescore(float* __restrict__ osims, float* __restrict__ oidx)
{
    int row = blockIdx.x;
    int tid = threadIdx.x, lane = tid & 31, warp = tid >> 5;
    __shared__ int    cand[NCAND];
    __shared__ double sval[NCAND];

    if(warp == 0){
        const float* s = g_sims + (size_t)row * NCP;
        float v[32];
        #pragma unroll
        for(int j = 0; j < 32; j++){
            int idx = j * 32 + lane;
            v[j] = (idx < NC) ? s[idx] : -3.0e38f;
        }
        for(int k = 0; k < NCAND; k++){
            float best = -3.0e38f; int bi = 1 << 20;
            #pragma unroll
            for(int j = 0; j < 32; j++){
                int idx = j * 32 + lane;
                if(v[j] > best){ best = v[j]; bi = idx; }
            }
            #pragma unroll
            for(int off = 16; off; off >>= 1){
                float ov = __shfl_xor_sync(0xffffffffu, best, off);
                int   oi = __shfl_xor_sync(0xffffffffu, bi,   off);
                if(ov > best || (ov == best && oi < bi)){ best = ov; bi = oi; }
            }
            if(lane == 0) cand[k] = bi;
            bi = __shfl_sync(0xffffffffu, bi, 0);
            if((bi & 31) == lane) v[bi >> 5] = -3.0e38f;
        }
    }
    __syncthreads();

    const float* mm = g_magf + (size_t)row * DD;
    double mn = g_mnorm_d[row];
    for(int c = warp; c < NCAND; c += 4){
        int idx = cand[c];
        const float* cm = g_cmagf + (size_t)idx * DD;
        double acc = 0.0;
        for(int d = lane; d < DD; d += 32)
            acc = fma((double)mm[d], (double)cm[d], acc);
        #pragma unroll
        for(int off = 16; off; off >>= 1)
            acc += __shfl_xor_sync(0xffffffffu, acc, off);
        if(lane == 0)
            sval[c] = acc / (mn * g_cnorm_d[idx]);
    }
    __syncthreads();

    if(tid == 0){
        bool used[NCAND];
        #pragma unroll
        for(int i = 0; i < NCAND; i++) used[i] = false;
        for(int k = 0; k < TOPK; k++){
            int b = -1;
            for(int i = 0; i < NCAND; i++){
                if(used[i]) continue;
                if(b < 0 || sval[i] > sval[b] ||
                   (sval[i] == sval[b] && cand[i] < cand[b])) b = i;
            }
            used[b] = true;
            osims[row * TOPK + k] = (float)sval[b];
            oidx [row * TOPK + k] = (float)cand[b];
        }
    }
}

// ---------------- tiled fp16 mma GEMM, NT: C[M,N] = A[M,K] @ B[N,K]^T ----------------
// NTERMS==3: acc = A0*B0 + A1*B0 + A0*B1  (hi/lo split for ~fp32 accuracy)
// 3-stage cp.async ring -> ONE __syncthreads per mainloop iteration.
// 8 warps (2 wm x 4 wn), warp tile (MT*16) x 32 — proven best HMMA operating point.
#define BN 128
#define BK 64
#define KP 72   // 144B row stride: 8-row ldmatrix offsets mod 128 = {0,16,..,112} conflict-free

struct Epi {
    float* out_f; __half* out_hi; __half* out_lo;
    const float* bias; const float* rinv; const float* cinv;
    int ldo; int nreal;
};

template<int NTERMS, int BMv>
__device__ __forceinline__ void load_tiles(const __half* __restrict__ A0, const __half* __restrict__ A1,
                                           const __half* __restrict__ B0, const __half* __restrict__ B1,
                                           int K, int kTiles, int it, int bm, int bn, int tid,
                                           __half* stg)
{
    int t  = it / kTiles;
    int kk = (it - t * kTiles) * BK;
    const __half* A  = (NTERMS == 3 && t == 1) ? A1 : A0;
    const __half* Bp = (NTERMS == 3 && t == 2) ? B1 : B0;
    __half* sA = stg;
    __half* sB = stg + BMv * KP;
    const int CH = (BMv + BN) * 8 / 256;   // 16B chunks per thread
    #pragma unroll
    for(int r = 0; r < CH; r++){
        int id  = tid + r * 256;
        int row = id >> 3, c = id & 7;
        if(row < BMv){
            CP_ASYNC(cvta_s(sA + row * KP + c * 8),
                     A  + (size_t)(bm * BMv + row) * K + kk + c * 8);
        } else {
            CP_ASYNC(cvta_s(sB + (row - BMv) * KP + c * 8),
                     Bp + (size_t)(bn * BN + (row - BMv)) * K + kk + c * 8);
        }
    }
    CP_COMMIT;
}

template<int MODE, int NTERMS, int SWAPG, int MT>
__global__ void __launch_bounds__(256, 2) gemm_nt(
    const __half* __restrict__ A0, const __half* __restrict__ A1,
    const __half* __restrict__ B0, const __half* __restrict__ B1,
    int K, Epi ep)
{
    const int BMv = MT * 32;
    const int STG = (BMv + BN) * KP;
    extern __shared__ __half sm[];

    const int tid = threadIdx.x;
    const int bn = SWAPG ? blockIdx.y : blockIdx.x;
    const int bm = SWAPG ? blockIdx.x : blockIdx.y;
    const int lane = tid & 31, warp = tid >> 5;
    const int wm = warp >> 2, wn = warp & 3;   // 2 x 4 warps

    const int kTiles = K / BK;
    const int total  = NTERMS * kTiles;

    float acc[MT][4][4];
    #pragma unroll
    for(int a = 0; a < MT; a++)
        #pragma unroll
        for(int b = 0; b < 4; b++)
            #pragma unroll
            for(int e = 0; e < 4; e++) acc[a][b][e] = 0.f;

    load_tiles<NTERMS, BMv>(A0, A1, B0, B1, K, kTiles, 0, bm, bn, tid, sm);
    load_tiles<NTERMS, BMv>(A0, A1, B0, B1, K, kTiles, 1, bm, bn, tid, sm + STG);

    for(int i = 0; i < total; i++){
        if(i < total - 1) CP_WAIT1; else CP_WAIT0;
        __syncthreads();
        if(i + 2 < total){
            int s = (i + 2) % 3;
            load_tiles<NTERMS, BMv>(A0, A1, B0, B1, K, kTiles, i + 2, bm, bn, tid,
                                    sm + s * STG);
        }
        const __half* cA = sm + (i % 3) * STG;
        const __half* cB = cA + BMv * KP;
        #pragma unroll
        for(int ks = 0; ks < 4; ks++){
            uint32_t a[MT][4], b[4][2];
            #pragma unroll
            for(int mi = 0; mi < MT; mi++){
                int row = wm * (MT * 16) + mi * 16 + (lane & 15);
                int col = ks * 16 + ((lane >> 4) & 1) * 8;
                uint32_t addr = cvta_s(cA + row * KP + col);
                asm volatile("ldmatrix.sync.aligned.m8n8.x4.shared.b16 {%0,%1,%2,%3},[%4];\n"
                    : "=r"(a[mi][0]), "=r"(a[mi][1]), "=r"(a[mi][2]), "=r"(a[mi][3]) : "r"(addr));
            }
            #pragma unroll
            for(int ni = 0; ni < 2; ni++){
                int row = wn * 32 + ni * 16 + (lane & 7) + ((lane >> 4) & 1) * 8;
                int col = ks * 16 + ((lane >> 3) & 1) * 8;
                uint32_t addr = cvta_s(cB + row * KP + col);
                uint32_t r0, r1, r2, r3;
                asm volatile("ldmatrix.sync.aligned.m8n8.x4.shared.b16 {%0,%1,%2,%3},[%4];\n"
                    : "=r"(r0), "=r"(r1), "=r"(r2), "=r"(r3) : "r"(addr));
                b[ni * 2][0] = r0; b[ni * 2][1] = r1;
                b[ni * 2 + 1][0] = r2; b[ni * 2 + 1][1] = r3;
            }
            #pragma unroll
            for(int mi = 0; mi < MT; mi++)
                #pragma unroll
                for(int nj = 0; nj < 4; nj++)
                    asm volatile("mma.sync.aligned.m16n8k16.row.col.f32.f16.f16.f32 "
                        "{%0,%1,%2,%3},{%4,%5,%6,%7},{%8,%9},{%0,%1,%2,%3};\n"
                        : "+f"(acc[mi][nj][0]), "+f"(acc[mi][nj][1]),
                          "+f"(acc[mi][nj][2]), "+f"(acc[mi][nj][3])
                        : "r"(a[mi][0]), "r"(a[mi][1]), "r"(a[mi][2]), "r"(a[mi][3]),
                          "r"(b[nj][0]), "r"(b[nj][1]));
        }
    }

    // epilogue
    const int groupID = lane >> 2, tid4 = lane & 3;
    #pragma unroll
    for(int mi = 0; mi < MT; mi++){
        #pragma unroll
        for(int nj = 0; nj < 4; nj++){
            if(MODE == 3){
                int r0 = bm * BMv + wm * (MT * 16) + mi * 16 + groupID;
                int c  = bn * BN + wn * 32 + nj * 8 + tid4 * 2;
                if(c < ep.nreal){
                    float bc0 = ep.bias[c], bc1 = ep.bias[c + 1];
                    float2 v0 = make_float2(acc[mi][nj][0] + bc0, acc[mi][nj][1] + bc1);
                    float2 v1 = make_float2(acc[mi][nj][2] + bc0, acc[mi][nj][3] + bc1);
                    *(float2*)&ep.out_f[(size_t)r0 * ep.nreal + c]       = v0;
                    *(float2*)&ep.out_f[(size_t)(r0 + 8) * ep.nreal + c] = v1;
                }
            } else {
                #pragma unroll
                for(int e = 0; e < 4; e++){
                    int r = bm * BMv + wm * (MT * 16) + mi * 16 + groupID + ((e >= 2) ? 8 : 0);
                    int c = bn * BN + wn * 32 + nj * 8 + tid4 * 2 + (e & 1);
                    float v = acc[mi][nj][e];
                    if(MODE == 0){                 // sims: scale by row/col reciprocal norms
                        ep.out_f[(size_t)r * ep.ldo + c] = v * ep.rinv[r] * ep.cinv[c];
                    } else if(MODE == 1){          // gelu, store hi/lo split
                        v = gelu_f(v + ep.bias[c]);
                        __half h = __float2half(v);
                        ep.out_hi[(size_t)r * ep.ldo + c] = h;
                        ep.out_lo[(size_t)r * ep.ldo + c] = __float2half(v - __half2float(h));
                    } else if(MODE == 2){          // gelu, store single half
                        v = gelu_f(v + ep.bias[c]);
                        ep.out_hi[(size_t)r * ep.ldo + c] = __float2half(v);
                    }
                }
            }
        }
    }
}

// ---------------- launch ----------------
extern "C" void kernel_launch(void* const* d_in, const int* in_sizes, int n_in,
                              void* d_out, int out_size)
{
    const float* sre = (const float*)d_in[0];
    const float* simg= (const float*)d_in[1];
    const float* cre = (const float*)d_in[2];
    const float* cim = (const float*)d_in[3];
    const float* W1  = (const float*)d_in[4];
    const float* b1  = (const float*)d_in[5];
    const float* W2  = (const float*)d_in[6];
    const float* b2  = (const float*)d_in[7];
    const float* W3  = (const float*)d_in[8];
    const float* b3  = (const float*)d_in[9];
    const float* W4  = (const float*)d_in[10];
    const float* b4  = (const float*)d_in[11];

    __half *xhi,*xlo,*mhi,*mlo,*chi,*clo,*w1hi,*w1lo,*w2hi,*w2lo,*w3hi,*w3lo,*w4t;
    __half *h1hi,*h1lo,*h2hi,*h2lo,*h3;
    float *minv,*cinv,*simsb;
    cudaGetSymbolAddress((void**)&xhi,  g_xhi);  cudaGetSymbolAddress((void**)&xlo,  g_xlo);
    cudaGetSymbolAddress((void**)&mhi,  g_mhi);  cudaGetSymbolAddress((void**)&mlo,  g_mlo);
    cudaGetSymbolAddress((void**)&chi,  g_chi);  cudaGetSymbolAddress((void**)&clo,  g_clo);
    cudaGetSymbolAddress((void**)&w1hi, g_w1hi); cudaGetSymbolAddress((void**)&w1lo, g_w1lo);
    cudaGetSymbolAddress((void**)&w2hi, g_w2hi); cudaGetSymbolAddress((void**)&w2lo, g_w2lo);
    cudaGetSymbolAddress((void**)&w3hi, g_w3hi); cudaGetSymbolAddress((void**)&w3lo, g_w3lo);
    cudaGetSymbolAddress((void**)&w4t,  g_w4t);
    cudaGetSymbolAddress((void**)&h1hi, g_h1hi); cudaGetSymbolAddress((void**)&h1lo, g_h1lo);
    cudaGetSymbolAddress((void**)&h2hi, g_h2hi); cudaGetSymbolAddress((void**)&h2lo, g_h2lo);
    cudaGetSymbolAddress((void**)&h3,   g_h3);
    cudaGetSymbolAddress((void**)&minv, g_minv); cudaGetSymbolAddress((void**)&cinv, g_cinv);
    cudaGetSymbolAddress((void**)&simsb,g_sims);

    float* out        = (float*)d_out;
    float* out_sims   = out;
    float* out_idx    = out + (size_t)HM * TOPK;
    float* out_logits = out + (size_t)2 * HM * TOPK;
    if(out_size == (int)((size_t)HM * NV)){   // logits-only layout fallback
        out_logits = out; out_sims = nullptr; out_idx = nullptr;
    }

    const int SM_SMALL = 3 * (64  + BN) * KP * (int)sizeof(__half);   // 82944
    const int SM_BIG   = 3 * (128 + BN) * KP * (int)sizeof(__half);   // 110592

    // one-time setup on the FIRST (uncaptured) correctness call
    static cudaStream_t s1 = 0;
    static cudaEvent_t evFork = 0, evW = 0, evX = 0, evS = 0;
    if(!s1){
        cudaFuncSetAttribute(gemm_nt<0,3,0,2>, cudaFuncAttributeMaxDynamicSharedMemorySize, SM_SMALL);
        cudaFuncSetAttribute(gemm_nt<1,3,0,2>, cudaFuncAttributeMaxDynamicSharedMemorySize, SM_SMALL);
        cudaFuncSetAttribute(gemm_nt<2,3,0,2>, cudaFuncAttributeMaxDynamicSharedMemorySize, SM_SMALL);
        cudaFuncSetAttribute(gemm_nt<3,1,1,4>, cudaFuncAttributeMaxDynamicSharedMemorySize, SM_BIG);
        cudaStreamCreateWithFlags(&s1, cudaStreamNonBlocking);
        cudaEventCreateWithFlags(&evFork, cudaEventDisableTiming);
        cudaEventCreateWithFlags(&evW,    cudaEventDisableTiming);
        cudaEventCreateWithFlags(&evX,    cudaEventDisableTiming);
        cudaEventCreateWithFlags(&evS,    cudaEventDisableTiming);
    }

    dim3 tb(32, 8);
    Epi e;

    // ---- fork side stream ----
    cudaEventRecord(evFork, 0);
    cudaStreamWaitEvent(s1, evFork, 0);

    // ---- s1: prep_c + W2/W3/W4 conversions ----
    prep_c_kernel<<<NCP, 256, 0, s1>>>(cre, cim);
    wconv_kernel<<<dim3(512/32, DD/32), tb, 0, s1>>>(W2, w2hi, w2lo, DD,  512, 512);
    wconv_kernel<<<dim3(DD/32,  512/32),tb, 0, s1>>>(W3, w3hi, w3lo, 512, DD,  DD);
    wconv_kernel<<<dim3(NVP/32, DD/32), tb, 0, s1>>>(W4, w4t, nullptr, DD, NV, NVP);
    cudaEventRecord(evW, s1);

    // ---- s0 (main): W1 + input prep ----
    wconv_kernel<<<dim3(DD/32,  K1/32), tb>>>(W1, w1hi, w1lo, K1,  DD,  DD);
    prep_x_kernel<<<HM, 256>>>(sre, simg);
    cudaEventRecord(evX, 0);
    cudaStreamWaitEvent(s1, evX, 0);

    // ---- s1: sims filter (3-term) + topk rescore ----
    if(out_sims){
        e = Epi{}; e.out_f = simsb; e.rinv = minv; e.cinv = cinv; e.ldo = NCP;
        gemm_nt<0,3,0,2><<<dim3(NCP/BN, HM/64), 256, SM_SMALL, s1>>>(mhi, mlo, chi, clo, DD, e);
        topk_rescore<<<HM, 128, 0, s1>>>(out_sims, out_idx);
    }
    cudaEventRecord(evS, s1);

    // ---- s0: L1 (needs only W1 + prep_x) ----
    e = Epi{}; e.out_hi = h1hi; e.out_lo = h1lo; e.bias = b1; e.ldo = DD;
    gemm_nt<1,3,0,2><<<dim3(DD/BN, HM/64), 256, SM_SMALL>>>(xhi, xlo, w1hi, w1lo, K1, e);

    cudaStreamWaitEvent(0, evW, 0);
    e = Epi{}; e.out_hi = h2hi; e.out_lo = h2lo; e.bias = b2; e.ldo = 512;
    gemm_nt<1,3,0,2><<<dim3(512/BN, HM/64), 256, SM_SMALL>>>(h1hi, h1lo, w2hi, w2lo, DD, e);
    e = Epi{}; e.out_hi = h3; e.bias = b3; e.ldo = DD;
    gemm_nt<2,3,0,2><<<dim3(DD/BN, HM/64), 256, SM_SMALL>>>(h2hi, h2lo, w3hi, w3lo, 512, e);

    // ---- s0: L4 — 8-warp MT=4 kernel, SWAPPED grid for W4t L2 reuse ----
    e = Epi{}; e.out_f = out_logits; e.bias = b4; e.nreal = NV;
    gemm_nt<3,1,1,4><<<dim3(HM/128, NVP/BN), 256, SM_BIG>>>(h3, nullptr, w4t, nullptr, DD, e);

    // ---- join ----
    cudaStreamWaitEvent(0, evS, 0);
}